// round 1
// baseline (speedup 1.0000x reference)
#include <cuda_runtime.h>
#include <math_constants.h>
#include <cstddef>

#define B_ 8
#define L_ 1024
#define C_ 1024
#define H_ 16
#define D_ 64
#define MAXSC 4.6051701859880914f  // log(100)

// Scratch (bss, no runtime allocation)
__device__ float g_qkv[B_ * L_ * 3 * C_];   // 96 MB  [b*l][3C]
__device__ float g_q[B_ * H_ * L_ * D_];    // 32 MB  [b,h,l,d]
__device__ float g_k[B_ * H_ * L_ * D_];    // 32 MB
__device__ float g_v[B_ * H_ * L_ * D_];    // 32 MB
__device__ float g_ao[B_ * L_ * C_];        // 32 MB  [b,l,c]

// ---------------------------------------------------------------------------
// GEMM: C[m,n] = sum_k A[m,k] * B[n,k] + bias(n)
// A: (M,K) row-major, B: (N,K) row-major (i.e. C = A * B^T)
// mode 0: bias = concat(q_bias, 0, v_bias) pattern over N=3C
// mode 1: bias = bias_q[n]
// 128x128 tile, BK=8, 256 threads, 8x8 micro-tile per thread.
// ---------------------------------------------------------------------------
__global__ __launch_bounds__(256) void gemm_kernel(
    const float* __restrict__ A, const float* __restrict__ Bm,
    float* __restrict__ Cm,
    const float* __restrict__ bias_q, const float* __restrict__ bias_v,
    int M, int N, int K, int mode)
{
    __shared__ float As[8][128];
    __shared__ float Bs[8][128];
    int t  = threadIdx.x;
    int ty = t >> 4, tx = t & 15;
    int m0 = blockIdx.y * 128, n0 = blockIdx.x * 128;

    float acc[8][8];
    #pragma unroll
    for (int i = 0; i < 8; i++)
        #pragma unroll
        for (int j = 0; j < 8; j++) acc[i][j] = 0.f;

    int lr = t >> 1;          // 0..127 row within tile
    int lc = (t & 1) * 4;     // 0 or 4
    const float* Ag = A  + (size_t)(m0 + lr) * K + lc;
    const float* Bg = Bm + (size_t)(n0 + lr) * K + lc;

    for (int k0 = 0; k0 < K; k0 += 8) {
        float4 av = *(const float4*)(Ag + k0);
        float4 bv = *(const float4*)(Bg + k0);
        As[lc + 0][lr] = av.x; As[lc + 1][lr] = av.y;
        As[lc + 2][lr] = av.z; As[lc + 3][lr] = av.w;
        Bs[lc + 0][lr] = bv.x; Bs[lc + 1][lr] = bv.y;
        Bs[lc + 2][lr] = bv.z; Bs[lc + 3][lr] = bv.w;
        __syncthreads();
        #pragma unroll
        for (int kk = 0; kk < 8; kk++) {
            float4 a0 = *(const float4*)&As[kk][ty * 4];
            float4 a1 = *(const float4*)&As[kk][ty * 4 + 64];
            float4 b0 = *(const float4*)&Bs[kk][tx * 4];
            float4 b1 = *(const float4*)&Bs[kk][tx * 4 + 64];
            float a[8] = {a0.x, a0.y, a0.z, a0.w, a1.x, a1.y, a1.z, a1.w};
            float b[8] = {b0.x, b0.y, b0.z, b0.w, b1.x, b1.y, b1.z, b1.w};
            #pragma unroll
            for (int i = 0; i < 8; i++)
                #pragma unroll
                for (int j = 0; j < 8; j++) acc[i][j] += a[i] * b[j];
        }
        __syncthreads();
    }

    #pragma unroll
    for (int i = 0; i < 8; i++) {
        int m = m0 + ty * 4 + (i & 3) + ((i >> 2) * 64);
        #pragma unroll
        for (int j = 0; j < 8; j++) {
            int n = n0 + tx * 4 + (j & 3) + ((j >> 2) * 64);
            float bv;
            if (mode == 0) {
                bv = (n < C_) ? bias_q[n] : ((n < 2 * C_) ? 0.f : bias_v[n - 2 * C_]);
            } else {
                bv = bias_q[n];
            }
            Cm[(size_t)m * N + n] = acc[i][j] + bv;
        }
    }
}

// ---------------------------------------------------------------------------
// Transform: l2norm(+scale) + RoPE for q,k; passthrough v.
// One warp per (b,l,h) row. Lane owns complex pair (2*lane, 2*lane+1).
// ---------------------------------------------------------------------------
__global__ __launch_bounds__(256) void transform_kernel(
    const float* __restrict__ freqs, const float* __restrict__ sml)
{
    int w    = blockIdx.x * 8 + (threadIdx.x >> 5);
    int lane = threadIdx.x & 31;
    int h = w & 15;
    int l = (w >> 4) & 1023;
    int b = w >> 14;

    const float* base = g_qkv + (size_t)(b * L_ + l) * (3 * C_);
    float2 q2 = ((const float2*)(base + 0 * C_ + h * D_))[lane];
    float2 k2 = ((const float2*)(base + 1 * C_ + h * D_))[lane];
    float2 v2 = ((const float2*)(base + 2 * C_ + h * D_))[lane];

    float qs = q2.x * q2.x + q2.y * q2.y;
    float ks = k2.x * k2.x + k2.y * k2.y;
    #pragma unroll
    for (int o = 16; o > 0; o >>= 1) {
        qs += __shfl_xor_sync(0xffffffffu, qs, o);
        ks += __shfl_xor_sync(0xffffffffu, ks, o);
    }
    float qinv = expf(fminf(sml[h], MAXSC)) / fmaxf(sqrtf(qs), 1e-12f);
    float kinv = 1.f / fmaxf(sqrtf(ks), 1e-12f);

    float2 fc = ((const float2*)(freqs + l * D_))[lane];  // cos, sin
    float qx = q2.x * qinv, qy = q2.y * qinv;
    float kx = k2.x * kinv, ky = k2.y * kinv;
    float2 qo = make_float2(qx * fc.x - qy * fc.y, qx * fc.y + qy * fc.x);
    float2 ko = make_float2(kx * fc.x - ky * fc.y, kx * fc.y + ky * fc.x);

    size_t oidx = (size_t)((b * H_ + h) * L_ + l) * D_;
    ((float2*)(g_q + oidx))[lane] = qo;
    ((float2*)(g_k + oidx))[lane] = ko;
    ((float2*)(g_v + oidx))[lane] = v2;
}

// ---------------------------------------------------------------------------
// Flash attention: block = (64 queries) x (D=64), key tiles of 64, online
// softmax staged in smem. 256 threads, 4x4 micro-tiles for S and O.
// smem: Qs[d][i], Ks[d][j], Vs[j][d], Ss[j][i] each 64x68 + m/l/corr.
// ---------------------------------------------------------------------------
#define SATT_STRIDE 68
__global__ __launch_bounds__(256) void attn_kernel(const float* __restrict__ bias,
                                                   float* __restrict__ AO)
{
    extern __shared__ float sm[];
    float* Qs = sm;
    float* Ks = Qs + 64 * SATT_STRIDE;
    float* Vs = Ks + 64 * SATT_STRIDE;
    float* Ss = Vs + 64 * SATT_STRIDE;
    float* m_s = Ss + 64 * SATT_STRIDE;
    float* l_s = m_s + 64;
    float* c_s = l_s + 64;

    int t  = threadIdx.x;
    int ty = t >> 4, tx = t & 15;
    int q0 = blockIdx.x * 64;
    int bh = blockIdx.y;
    int b = bh >> 4, h = bh & 15;

    const float* Qg = g_q + (size_t)bh * L_ * D_;
    const float* Kg = g_k + (size_t)bh * L_ * D_;
    const float* Vg = g_v + (size_t)bh * L_ * D_;

    // Load Q tile transposed: Qs[d][i]
    {
        int i0 = t >> 4;
        int db = (t & 15) * 4;
        #pragma unroll
        for (int it = 0; it < 4; it++) {
            int i = i0 + it * 16;
            float4 v = *(const float4*)(Qg + (size_t)(q0 + i) * D_ + db);
            Qs[(db + 0) * SATT_STRIDE + i] = v.x;
            Qs[(db + 1) * SATT_STRIDE + i] = v.y;
            Qs[(db + 2) * SATT_STRIDE + i] = v.z;
            Qs[(db + 3) * SATT_STRIDE + i] = v.w;
        }
    }
    if (t < 64) { m_s[t] = -CUDART_INF_F; l_s[t] = 0.f; }

    float o[4][4];
    #pragma unroll
    for (int i = 0; i < 4; i++)
        #pragma unroll
        for (int j = 0; j < 4; j++) o[i][j] = 0.f;
    __syncthreads();

    for (int k0 = 0; k0 < L_; k0 += 64) {
        // Load K transposed (Ks[d][j]) and V direct (Vs[j][d])
        {
            int i0 = t >> 4;
            int db = (t & 15) * 4;
            #pragma unroll
            for (int it = 0; it < 4; it++) {
                int j = i0 + it * 16;
                float4 kv = *(const float4*)(Kg + (size_t)(k0 + j) * D_ + db);
                Ks[(db + 0) * SATT_STRIDE + j] = kv.x;
                Ks[(db + 1) * SATT_STRIDE + j] = kv.y;
                Ks[(db + 2) * SATT_STRIDE + j] = kv.z;
                Ks[(db + 3) * SATT_STRIDE + j] = kv.w;
                float4 vv = *(const float4*)(Vg + (size_t)(k0 + j) * D_ + db);
                *(float4*)&Vs[j * SATT_STRIDE + db] = vv;
            }
        }
        __syncthreads();

        // S = Q K^T (4x4 micro-tile per thread)
        float s[4][4];
        #pragma unroll
        for (int i = 0; i < 4; i++)
            #pragma unroll
            for (int j = 0; j < 4; j++) s[i][j] = 0.f;
        #pragma unroll
        for (int d = 0; d < 64; d++) {
            float4 a  = *(const float4*)&Qs[d * SATT_STRIDE + ty * 4];
            float4 bv = *(const float4*)&Ks[d * SATT_STRIDE + tx * 4];
            float av[4] = {a.x, a.y, a.z, a.w};
            float bb[4] = {bv.x, bv.y, bv.z, bv.w};
            #pragma unroll
            for (int i = 0; i < 4; i++)
                #pragma unroll
                for (int j = 0; j < 4; j++) s[i][j] += av[i] * bb[j];
        }
        // Add attn_bias, store S transposed: Ss[j][i]
        #pragma unroll
        for (int j = 0; j < 4; j++) {
            int kg = k0 + tx * 4 + j;
            float4 col;
            col.x = s[0][j] + bias[(size_t)(q0 + ty * 4 + 0) * L_ + kg];
            col.y = s[1][j] + bias[(size_t)(q0 + ty * 4 + 1) * L_ + kg];
            col.z = s[2][j] + bias[(size_t)(q0 + ty * 4 + 2) * L_ + kg];
            col.w = s[3][j] + bias[(size_t)(q0 + ty * 4 + 3) * L_ + kg];
            *(float4*)&Ss[(tx * 4 + j) * SATT_STRIDE + ty * 4] = col;
        }
        __syncthreads();

        // Online softmax: 4 threads per row
        {
            int r = t >> 2, sub = t & 3;
            float mx = -CUDART_INF_F;
            #pragma unroll
            for (int jj = 0; jj < 16; jj++)
                mx = fmaxf(mx, Ss[(sub * 16 + jj) * SATT_STRIDE + r]);
            mx = fmaxf(mx, __shfl_xor_sync(0xffffffffu, mx, 1));
            mx = fmaxf(mx, __shfl_xor_sync(0xffffffffu, mx, 2));
            float m_old = m_s[r];
            float m_new = fmaxf(m_old, mx);
            float sum = 0.f;
            #pragma unroll
            for (int jj = 0; jj < 16; jj++) {
                int idx = (sub * 16 + jj) * SATT_STRIDE + r;
                float p = __expf(Ss[idx] - m_new);
                Ss[idx] = p;
                sum += p;
            }
            sum += __shfl_xor_sync(0xffffffffu, sum, 1);
            sum += __shfl_xor_sync(0xffffffffu, sum, 2);
            if (sub == 0) {
                float corr = __expf(m_old - m_new);
                c_s[r] = corr;
                l_s[r] = l_s[r] * corr + sum;
                m_s[r] = m_new;
            }
        }
        __syncthreads();

        // Rescale O, accumulate P*V
        float corr[4];
        #pragma unroll
        for (int i = 0; i < 4; i++) corr[i] = c_s[ty * 4 + i];
        #pragma unroll
        for (int i = 0; i < 4; i++)
            #pragma unroll
            for (int j = 0; j < 4; j++) o[i][j] *= corr[i];
        #pragma unroll
        for (int j = 0; j < 64; j++) {
            float4 a  = *(const float4*)&Ss[j * SATT_STRIDE + ty * 4];
            float4 bv = *(const float4*)&Vs[j * SATT_STRIDE + tx * 4];
            float av[4] = {a.x, a.y, a.z, a.w};
            float bb[4] = {bv.x, bv.y, bv.z, bv.w};
            #pragma unroll
            for (int i = 0; i < 4; i++)
                #pragma unroll
                for (int jj = 0; jj < 4; jj++) o[i][jj] += av[i] * bb[jj];
        }
        __syncthreads();
    }

    // Epilogue: divide by l, write to [b, q, h*64+d]
    #pragma unroll
    for (int i = 0; i < 4; i++) {
        int q = q0 + ty * 4 + i;
        float inv = 1.f / l_s[ty * 4 + i];
        float4 r = make_float4(o[i][0] * inv, o[i][1] * inv,
                               o[i][2] * inv, o[i][3] * inv);
        *(float4*)&AO[(size_t)(b * L_ + q) * C_ + h * D_ + tx * 4] = r;
    }
}

// ---------------------------------------------------------------------------
extern "C" void kernel_launch(void* const* d_in, const int* in_sizes, int n_in,
                              void* d_out, int out_size)
{
    const float* x         = (const float*)d_in[0];
    const float* freqs     = (const float*)d_in[1];
    const float* attn_bias = (const float*)d_in[2];
    const float* W_qkv     = (const float*)d_in[3];
    const float* q_bias    = (const float*)d_in[4];
    const float* v_bias    = (const float*)d_in[5];
    const float* sml       = (const float*)d_in[6];
    const float* W_proj    = (const float*)d_in[7];
    const float* b_proj    = (const float*)d_in[8];
    float* out = (float*)d_out;

    void* p;
    cudaGetSymbolAddress(&p, g_qkv); float* qkv = (float*)p;
    cudaGetSymbolAddress(&p, g_ao);  float* ao  = (float*)p;

    // 1) QKV GEMM: (8192 x 1024) @ (3072 x 1024)^T + concat bias
    gemm_kernel<<<dim3(3 * C_ / 128, B_ * L_ / 128), 256>>>(
        x, W_qkv, qkv, q_bias, v_bias, B_ * L_, 3 * C_, C_, 0);

    // 2) l2norm + scale + RoPE -> g_q/g_k/g_v
    transform_kernel<<<(B_ * L_ * H_) / 8, 256>>>(freqs, sml);

    // 3) Flash attention
    int smem = (4 * 64 * SATT_STRIDE + 3 * 64) * (int)sizeof(float);  // 70400 B
    cudaFuncSetAttribute(attn_kernel, cudaFuncAttributeMaxDynamicSharedMemorySize, smem);
    attn_kernel<<<dim3(L_ / 64, B_ * H_), 256, smem>>>(attn_bias, ao);

    // 4) Proj GEMM: (8192 x 1024) @ (1024 x 1024)^T + b_proj
    gemm_kernel<<<dim3(C_ / 128, B_ * L_ / 128), 256>>>(
        ao, W_proj, out, b_proj, nullptr, B_ * L_, C_, C_, 1);
}

// round 4
// speedup vs baseline: 1.3781x; 1.3781x over previous
#include <cuda_runtime.h>
#include <cuda_bf16.h>
#include <math_constants.h>
#include <cstdint>
#include <cstddef>

#define B_ 8
#define L_ 1024
#define C_ 1024
#define H_ 16
#define D_ 64
#define MAXSC 4.6051701859880914f  // log(100)

// ---------------------------------------------------------------------------
// Scratch (bss, no runtime allocation)
// ---------------------------------------------------------------------------
__device__ float g_qkv[B_ * L_ * 3 * C_];   // 96 MB  [b*l][3C]
__device__ float g_q[B_ * H_ * L_ * D_];    // 32 MB  [b,h,l,d]
__device__ float g_k[B_ * H_ * L_ * D_];    // 32 MB
__device__ float g_v[B_ * H_ * L_ * D_];    // 32 MB
__device__ float g_ao[B_ * L_ * C_];        // 32 MB  [b,l,c]

__device__ __nv_bfloat16 g_xhi[B_ * L_ * C_];
__device__ __nv_bfloat16 g_xlo[B_ * L_ * C_];
__device__ __nv_bfloat16 g_wqh[3 * C_ * C_];
__device__ __nv_bfloat16 g_wql[3 * C_ * C_];
__device__ __nv_bfloat16 g_aoh[B_ * L_ * C_];
__device__ __nv_bfloat16 g_aol[B_ * L_ * C_];
__device__ __nv_bfloat16 g_wph[C_ * C_];
__device__ __nv_bfloat16 g_wpl[C_ * C_];

// ---------------------------------------------------------------------------
// fp32 -> (hi, lo) bf16 split
// ---------------------------------------------------------------------------
__global__ __launch_bounds__(256) void conv_split_kernel(
    const float* __restrict__ src, __nv_bfloat16* __restrict__ hi,
    __nv_bfloat16* __restrict__ lo, int n4)
{
    int i = blockIdx.x * blockDim.x + threadIdx.x;
    if (i >= n4) return;
    float4 v = ((const float4*)src)[i];
    __nv_bfloat16 h0 = __float2bfloat16(v.x);
    __nv_bfloat16 h1 = __float2bfloat16(v.y);
    __nv_bfloat16 h2 = __float2bfloat16(v.z);
    __nv_bfloat16 h3 = __float2bfloat16(v.w);
    __nv_bfloat16 l0 = __float2bfloat16(v.x - __bfloat162float(h0));
    __nv_bfloat16 l1 = __float2bfloat16(v.y - __bfloat162float(h1));
    __nv_bfloat16 l2 = __float2bfloat16(v.z - __bfloat162float(h2));
    __nv_bfloat16 l3 = __float2bfloat16(v.w - __bfloat162float(h3));
    ((__nv_bfloat162*)hi)[2 * i]     = __nv_bfloat162(h0, h1);
    ((__nv_bfloat162*)hi)[2 * i + 1] = __nv_bfloat162(h2, h3);
    ((__nv_bfloat162*)lo)[2 * i]     = __nv_bfloat162(l0, l1);
    ((__nv_bfloat162*)lo)[2 * i + 1] = __nv_bfloat162(l2, l3);
}

// ---------------------------------------------------------------------------
// mma.sync bf16 helper (baseline PTX, works on sm_103 family target)
// ---------------------------------------------------------------------------
__device__ __forceinline__ void mma16816(float* c, const uint32_t* a,
                                         const uint32_t* b)
{
    asm volatile(
        "mma.sync.aligned.m16n8k16.row.col.f32.bf16.bf16.f32 "
        "{%0,%1,%2,%3}, {%4,%5,%6,%7}, {%8,%9}, {%0,%1,%2,%3};"
        : "+f"(c[0]), "+f"(c[1]), "+f"(c[2]), "+f"(c[3])
        : "r"(a[0]), "r"(a[1]), "r"(a[2]), "r"(a[3]), "r"(b[0]), "r"(b[1]));
}

// ---------------------------------------------------------------------------
// HMMA GEMM: C[m,n] = sum_k A[m,k]*B[n,k] + bias(n)
// A,B pre-split (hi,lo) bf16.  C = Ahi*Bhi + Ahi*Blo + Alo*Bhi (fp32 acc).
// CTA 128x128, K chunk 32, 256 threads (8 warps in 4x2: warp tile 32Mx64N).
// smem: 4 matrices [128][40] bf16 (80B row stride: conflict-free frag loads).
// mode 0: bias = concat(q_bias, 0, v_bias); mode 1: bias = bias_q[n].
// ---------------------------------------------------------------------------
#define SSTRIDE 40
__global__ __launch_bounds__(256) void gemm_mma_kernel(
    const __nv_bfloat16* __restrict__ Ahi, const __nv_bfloat16* __restrict__ Alo,
    const __nv_bfloat16* __restrict__ Bhi, const __nv_bfloat16* __restrict__ Blo,
    float* __restrict__ Cm,
    const float* __restrict__ bias_q, const float* __restrict__ bias_v,
    int N, int K, int mode)
{
    extern __shared__ __align__(16) __nv_bfloat16 sm[];
    __nv_bfloat16* sAh = sm;
    __nv_bfloat16* sAl = sAh + 128 * SSTRIDE;
    __nv_bfloat16* sBh = sAl + 128 * SSTRIDE;
    __nv_bfloat16* sBl = sBh + 128 * SSTRIDE;

    int t = threadIdx.x;
    int wid = t >> 5, lane = t & 31;
    int wm = wid & 3, wn = wid >> 2;
    int m0 = blockIdx.y * 128, n0 = blockIdx.x * 128;

    float acc[2][8][4];
    #pragma unroll
    for (int i = 0; i < 2; i++)
        #pragma unroll
        for (int j = 0; j < 8; j++)
            #pragma unroll
            for (int u = 0; u < 4; u++) acc[i][j][u] = 0.f;

    int qrow = lane >> 2;        // 0..7
    int qk   = (lane & 3) * 2;   // 0,2,4,6

    for (int k0 = 0; k0 < K; k0 += 32) {
        // Load 4 matrices: 128 rows x 32 bf16 (64B) each; 512 16B-chunks each.
        #pragma unroll
        for (int i = 0; i < 2; i++) {
            int c = t + i * 256;
            int row = c >> 2, seg = c & 3;
            size_t ga = (size_t)(m0 + row) * K + k0 + seg * 8;
            size_t gb = (size_t)(n0 + row) * K + k0 + seg * 8;
            int so = row * SSTRIDE + seg * 8;
            *(uint4*)(sAh + so) = *(const uint4*)(Ahi + ga);
            *(uint4*)(sAl + so) = *(const uint4*)(Alo + ga);
            *(uint4*)(sBh + so) = *(const uint4*)(Bhi + gb);
            *(uint4*)(sBl + so) = *(const uint4*)(Blo + gb);
        }
        __syncthreads();

        #pragma unroll
        for (int ks = 0; ks < 2; ks++) {
            int kk = ks * 16 + qk;
            uint32_t afh[2][4], afl[2][4];
            #pragma unroll
            for (int mf = 0; mf < 2; mf++) {
                int r = wm * 32 + mf * 16 + qrow;
                afh[mf][0] = *(const uint32_t*)(sAh + r * SSTRIDE + kk);
                afh[mf][1] = *(const uint32_t*)(sAh + (r + 8) * SSTRIDE + kk);
                afh[mf][2] = *(const uint32_t*)(sAh + r * SSTRIDE + kk + 8);
                afh[mf][3] = *(const uint32_t*)(sAh + (r + 8) * SSTRIDE + kk + 8);
                afl[mf][0] = *(const uint32_t*)(sAl + r * SSTRIDE + kk);
                afl[mf][1] = *(const uint32_t*)(sAl + (r + 8) * SSTRIDE + kk);
                afl[mf][2] = *(const uint32_t*)(sAl + r * SSTRIDE + kk + 8);
                afl[mf][3] = *(const uint32_t*)(sAl + (r + 8) * SSTRIDE + kk + 8);
            }
            uint32_t bfh[8][2], bfl[8][2];
            #pragma unroll
            for (int nf = 0; nf < 8; nf++) {
                int nrow = wn * 64 + nf * 8 + qrow;
                bfh[nf][0] = *(const uint32_t*)(sBh + nrow * SSTRIDE + kk);
                bfh[nf][1] = *(const uint32_t*)(sBh + nrow * SSTRIDE + kk + 8);
                bfl[nf][0] = *(const uint32_t*)(sBl + nrow * SSTRIDE + kk);
                bfl[nf][1] = *(const uint32_t*)(sBl + nrow * SSTRIDE + kk + 8);
            }
            #pragma unroll
            for (int mf = 0; mf < 2; mf++)
                #pragma unroll
                for (int nf = 0; nf < 8; nf++) {
                    mma16816(acc[mf][nf], afh[mf], bfh[nf]);
                    mma16816(acc[mf][nf], afh[mf], bfl[nf]);
                    mma16816(acc[mf][nf], afl[mf], bfh[nf]);
                }
        }
        __syncthreads();
    }

    // Epilogue: c0,c1 at (row, col..col+1); c2,c3 at (row+8, ...)
    #pragma unroll
    for (int mf = 0; mf < 2; mf++) {
        #pragma unroll
        for (int nf = 0; nf < 8; nf++) {
            int row = m0 + wm * 32 + mf * 16 + qrow;
            int col = n0 + wn * 64 + nf * 8 + qk;
            float bv0, bv1;
            if (mode == 0) {
                bv0 = (col < C_) ? bias_q[col]
                    : ((col < 2 * C_) ? 0.f : bias_v[col - 2 * C_]);
                bv1 = (col + 1 < C_) ? bias_q[col + 1]
                    : ((col + 1 < 2 * C_) ? 0.f : bias_v[col + 1 - 2 * C_]);
            } else {
                bv0 = bias_q[col];
                bv1 = bias_q[col + 1];
            }
            *(float2*)(Cm + (size_t)row * N + col) =
                make_float2(acc[mf][nf][0] + bv0, acc[mf][nf][1] + bv1);
            *(float2*)(Cm + (size_t)(row + 8) * N + col) =
                make_float2(acc[mf][nf][2] + bv0, acc[mf][nf][3] + bv1);
        }
    }
}

// ---------------------------------------------------------------------------
// Transform: l2norm(+scale) + RoPE for q,k; passthrough v.
// ---------------------------------------------------------------------------
__global__ __launch_bounds__(256) void transform_kernel(
    const float* __restrict__ freqs, const float* __restrict__ sml)
{
    int w    = blockIdx.x * 8 + (threadIdx.x >> 5);
    int lane = threadIdx.x & 31;
    int h = w & 15;
    int l = (w >> 4) & 1023;
    int b = w >> 14;

    const float* base = g_qkv + (size_t)(b * L_ + l) * (3 * C_);
    float2 q2 = ((const float2*)(base + 0 * C_ + h * D_))[lane];
    float2 k2 = ((const float2*)(base + 1 * C_ + h * D_))[lane];
    float2 v2 = ((const float2*)(base + 2 * C_ + h * D_))[lane];

    float qs = q2.x * q2.x + q2.y * q2.y;
    float ks = k2.x * k2.x + k2.y * k2.y;
    #pragma unroll
    for (int o = 16; o > 0; o >>= 1) {
        qs += __shfl_xor_sync(0xffffffffu, qs, o);
        ks += __shfl_xor_sync(0xffffffffu, ks, o);
    }
    float qinv = expf(fminf(sml[h], MAXSC)) / fmaxf(sqrtf(qs), 1e-12f);
    float kinv = 1.f / fmaxf(sqrtf(ks), 1e-12f);

    float2 fc = ((const float2*)(freqs + l * D_))[lane];  // cos, sin
    float qx = q2.x * qinv, qy = q2.y * qinv;
    float kx = k2.x * kinv, ky = k2.y * kinv;
    float2 qo = make_float2(qx * fc.x - qy * fc.y, qx * fc.y + qy * fc.x);
    float2 ko = make_float2(kx * fc.x - ky * fc.y, kx * fc.y + ky * fc.x);

    size_t oidx = (size_t)((b * H_ + h) * L_ + l) * D_;
    ((float2*)(g_q + oidx))[lane] = qo;
    ((float2*)(g_k + oidx))[lane] = ko;
    ((float2*)(g_v + oidx))[lane] = v2;
}

// ---------------------------------------------------------------------------
// Flash attention (fp32 SIMT — R1 passing version, unchanged)
// ---------------------------------------------------------------------------
#define SATT_STRIDE 68
__global__ __launch_bounds__(256) void attn_kernel(const float* __restrict__ bias,
                                                   float* __restrict__ AO)
{
    extern __shared__ float smf[];
    float* Qs = smf;
    float* Ks = Qs + 64 * SATT_STRIDE;
    float* Vs = Ks + 64 * SATT_STRIDE;
    float* Ss = Vs + 64 * SATT_STRIDE;
    float* m_s = Ss + 64 * SATT_STRIDE;
    float* l_s = m_s + 64;
    float* c_s = l_s + 64;

    int t  = threadIdx.x;
    int ty = t >> 4, tx = t & 15;
    int q0 = blockIdx.x * 64;
    int bh = blockIdx.y;
    int b = bh >> 4, h = bh & 15;

    const float* Qg = g_q + (size_t)bh * L_ * D_;
    const float* Kg = g_k + (size_t)bh * L_ * D_;
    const float* Vg = g_v + (size_t)bh * L_ * D_;

    {
        int i0 = t >> 4;
        int db = (t & 15) * 4;
        #pragma unroll
        for (int it = 0; it < 4; it++) {
            int i = i0 + it * 16;
            float4 v = *(const float4*)(Qg + (size_t)(q0 + i) * D_ + db);
            Qs[(db + 0) * SATT_STRIDE + i] = v.x;
            Qs[(db + 1) * SATT_STRIDE + i] = v.y;
            Qs[(db + 2) * SATT_STRIDE + i] = v.z;
            Qs[(db + 3) * SATT_STRIDE + i] = v.w;
        }
    }
    if (t < 64) { m_s[t] = -CUDART_INF_F; l_s[t] = 0.f; }

    float o[4][4];
    #pragma unroll
    for (int i = 0; i < 4; i++)
        #pragma unroll
        for (int j = 0; j < 4; j++) o[i][j] = 0.f;
    __syncthreads();

    for (int k0 = 0; k0 < L_; k0 += 64) {
        {
            int i0 = t >> 4;
            int db = (t & 15) * 4;
            #pragma unroll
            for (int it = 0; it < 4; it++) {
                int j = i0 + it * 16;
                float4 kv = *(const float4*)(Kg + (size_t)(k0 + j) * D_ + db);
                Ks[(db + 0) * SATT_STRIDE + j] = kv.x;
                Ks[(db + 1) * SATT_STRIDE + j] = kv.y;
                Ks[(db + 2) * SATT_STRIDE + j] = kv.z;
                Ks[(db + 3) * SATT_STRIDE + j] = kv.w;
                float4 vv = *(const float4*)(Vg + (size_t)(k0 + j) * D_ + db);
                *(float4*)&Vs[j * SATT_STRIDE + db] = vv;
            }
        }
        __syncthreads();

        float s[4][4];
        #pragma unroll
        for (int i = 0; i < 4; i++)
            #pragma unroll
            for (int j = 0; j < 4; j++) s[i][j] = 0.f;
        #pragma unroll
        for (int d = 0; d < 64; d++) {
            float4 a  = *(const float4*)&Qs[d * SATT_STRIDE + ty * 4];
            float4 bv = *(const float4*)&Ks[d * SATT_STRIDE + tx * 4];
            float av[4] = {a.x, a.y, a.z, a.w};
            float bb[4] = {bv.x, bv.y, bv.z, bv.w};
            #pragma unroll
            for (int i = 0; i < 4; i++)
                #pragma unroll
                for (int j = 0; j < 4; j++) s[i][j] += av[i] * bb[j];
        }
        #pragma unroll
        for (int j = 0; j < 4; j++) {
            int kg = k0 + tx * 4 + j;
            float4 col;
            col.x = s[0][j] + bias[(size_t)(q0 + ty * 4 + 0) * L_ + kg];
            col.y = s[1][j] + bias[(size_t)(q0 + ty * 4 + 1) * L_ + kg];
            col.z = s[2][j] + bias[(size_t)(q0 + ty * 4 + 2) * L_ + kg];
            col.w = s[3][j] + bias[(size_t)(q0 + ty * 4 + 3) * L_ + kg];
            *(float4*)&Ss[(tx * 4 + j) * SATT_STRIDE + ty * 4] = col;
        }
        __syncthreads();

        {
            int r = t >> 2, sub = t & 3;
            float mx = -CUDART_INF_F;
            #pragma unroll
            for (int jj = 0; jj < 16; jj++)
                mx = fmaxf(mx, Ss[(sub * 16 + jj) * SATT_STRIDE + r]);
            mx = fmaxf(mx, __shfl_xor_sync(0xffffffffu, mx, 1));
            mx = fmaxf(mx, __shfl_xor_sync(0xffffffffu, mx, 2));
            float m_old = m_s[r];
            float m_new = fmaxf(m_old, mx);
            float sum = 0.f;
            #pragma unroll
            for (int jj = 0; jj < 16; jj++) {
                int idx = (sub * 16 + jj) * SATT_STRIDE + r;
                float p = __expf(Ss[idx] - m_new);
                Ss[idx] = p;
                sum += p;
            }
            sum += __shfl_xor_sync(0xffffffffu, sum, 1);
            sum += __shfl_xor_sync(0xffffffffu, sum, 2);
            if (sub == 0) {
                float corr = __expf(m_old - m_new);
                c_s[r] = corr;
                l_s[r] = l_s[r] * corr + sum;
                m_s[r] = m_new;
            }
        }
        __syncthreads();

        float corr[4];
        #pragma unroll
        for (int i = 0; i < 4; i++) corr[i] = c_s[ty * 4 + i];
        #pragma unroll
        for (int i = 0; i < 4; i++)
            #pragma unroll
            for (int j = 0; j < 4; j++) o[i][j] *= corr[i];
        #pragma unroll
        for (int j = 0; j < 64; j++) {
            float4 a  = *(const float4*)&Ss[j * SATT_STRIDE + ty * 4];
            float4 bv = *(const float4*)&Vs[j * SATT_STRIDE + tx * 4];
            float av[4] = {a.x, a.y, a.z, a.w};
            float bb[4] = {bv.x, bv.y, bv.z, bv.w};
            #pragma unroll
            for (int i = 0; i < 4; i++)
                #pragma unroll
                for (int jj = 0; jj < 4; jj++) o[i][jj] += av[i] * bb[jj];
        }
        __syncthreads();
    }

    #pragma unroll
    for (int i = 0; i < 4; i++) {
        int q = q0 + ty * 4 + i;
        float inv = 1.f / l_s[ty * 4 + i];
        float4 r = make_float4(o[i][0] * inv, o[i][1] * inv,
                               o[i][2] * inv, o[i][3] * inv);
        *(float4*)&AO[(size_t)(b * L_ + q) * C_ + h * D_ + tx * 4] = r;
    }
}

// ---------------------------------------------------------------------------
extern "C" void kernel_launch(void* const* d_in, const int* in_sizes, int n_in,
                              void* d_out, int out_size)
{
    const float* x         = (const float*)d_in[0];
    const float* freqs     = (const float*)d_in[1];
    const float* attn_bias = (const float*)d_in[2];
    const float* W_qkv     = (const float*)d_in[3];
    const float* q_bias    = (const float*)d_in[4];
    const float* v_bias    = (const float*)d_in[5];
    const float* sml       = (const float*)d_in[6];
    const float* W_proj    = (const float*)d_in[7];
    const float* b_proj    = (const float*)d_in[8];
    float* out = (float*)d_out;

    void* p;
    cudaGetSymbolAddress(&p, g_qkv); float* qkv = (float*)p;
    cudaGetSymbolAddress(&p, g_ao);  float* ao  = (float*)p;
    cudaGetSymbolAddress(&p, g_xhi); __nv_bfloat16* xhi = (__nv_bfloat16*)p;
    cudaGetSymbolAddress(&p, g_xlo); __nv_bfloat16* xlo = (__nv_bfloat16*)p;
    cudaGetSymbolAddress(&p, g_wqh); __nv_bfloat16* wqh = (__nv_bfloat16*)p;
    cudaGetSymbolAddress(&p, g_wql); __nv_bfloat16* wql = (__nv_bfloat16*)p;
    cudaGetSymbolAddress(&p, g_aoh); __nv_bfloat16* aoh = (__nv_bfloat16*)p;
    cudaGetSymbolAddress(&p, g_aol); __nv_bfloat16* aol = (__nv_bfloat16*)p;
    cudaGetSymbolAddress(&p, g_wph); __nv_bfloat16* wph = (__nv_bfloat16*)p;
    cudaGetSymbolAddress(&p, g_wpl); __nv_bfloat16* wpl = (__nv_bfloat16*)p;

    int gsm = 4 * 128 * SSTRIDE * (int)sizeof(__nv_bfloat16);  // 40960
    int asmem = (4 * 64 * SATT_STRIDE + 3 * 64) * (int)sizeof(float);
    static bool attr_set = false;
    if (!attr_set) {
        cudaFuncSetAttribute(gemm_mma_kernel,
                             cudaFuncAttributeMaxDynamicSharedMemorySize, gsm);
        cudaFuncSetAttribute(attn_kernel,
                             cudaFuncAttributeMaxDynamicSharedMemorySize, asmem);
        attr_set = true;
    }

    // 0) Split fp32 -> bf16 hi/lo
    conv_split_kernel<<<(B_ * L_ * C_ / 4 + 255) / 256, 256>>>(x, xhi, xlo, B_ * L_ * C_ / 4);
    conv_split_kernel<<<(3 * C_ * C_ / 4 + 255) / 256, 256>>>(W_qkv, wqh, wql, 3 * C_ * C_ / 4);
    conv_split_kernel<<<(C_ * C_ / 4 + 255) / 256, 256>>>(W_proj, wph, wpl, C_ * C_ / 4);

    // 1) QKV GEMM (HMMA): (8192 x 1024) @ (3072 x 1024)^T + concat bias
    gemm_mma_kernel<<<dim3(3 * C_ / 128, B_ * L_ / 128), 256, gsm>>>(
        xhi, xlo, wqh, wql, qkv, q_bias, v_bias, 3 * C_, C_, 0);

    // 2) l2norm + scale + RoPE -> g_q/g_k/g_v
    transform_kernel<<<(B_ * L_ * H_) / 8, 256>>>(freqs, sml);

    // 3) Flash attention (fp32)
    attn_kernel<<<dim3(L_ / 64, B_ * H_), 256, asmem>>>(attn_bias, ao);

    // 4) Split attention output, proj GEMM (HMMA)
    conv_split_kernel<<<(B_ * L_ * C_ / 4 + 255) / 256, 256>>>(ao, aoh, aol, B_ * L_ * C_ / 4);
    gemm_mma_kernel<<<dim3(C_ / 128, B_ * L_ / 128), 256, gsm>>>(
        aoh, aol, wph, wpl, out, b_proj, nullptr, C_, C_, 1);
}

// round 5
// speedup vs baseline: 2.2635x; 1.6425x over previous
#include <cuda_runtime.h>
#include <cuda_bf16.h>
#include <math_constants.h>
#include <cstdint>
#include <cstddef>

#define B_ 8
#define L_ 1024
#define C_ 1024
#define H_ 16
#define D_ 64
#define MAXSC 4.6051701859880914f  // log(100)

// ---------------------------------------------------------------------------
// Scratch (bss, no runtime allocation)
// ---------------------------------------------------------------------------
__device__ float g_qkv[B_ * L_ * 3 * C_];   // 96 MB  [b*l][3C]

__device__ __nv_bfloat16 g_xhi[B_ * L_ * C_];
__device__ __nv_bfloat16 g_xlo[B_ * L_ * C_];
__device__ __nv_bfloat16 g_wqh[3 * C_ * C_];
__device__ __nv_bfloat16 g_wql[3 * C_ * C_];
__device__ __nv_bfloat16 g_wph[C_ * C_];
__device__ __nv_bfloat16 g_wpl[C_ * C_];

// q/k/v hi/lo, [b,h,l,d] bf16
__device__ __nv_bfloat16 g_qh[B_ * H_ * L_ * D_];
__device__ __nv_bfloat16 g_ql[B_ * H_ * L_ * D_];
__device__ __nv_bfloat16 g_kh[B_ * H_ * L_ * D_];
__device__ __nv_bfloat16 g_kl[B_ * H_ * L_ * D_];
__device__ __nv_bfloat16 g_vh[B_ * H_ * L_ * D_];
__device__ __nv_bfloat16 g_vl[B_ * H_ * L_ * D_];

// attention output hi/lo, [b,l,c]
__device__ __nv_bfloat16 g_aoh[B_ * L_ * C_];
__device__ __nv_bfloat16 g_aol[B_ * L_ * C_];

// ---------------------------------------------------------------------------
// Helpers
// ---------------------------------------------------------------------------
__device__ __forceinline__ uint32_t smem_u32(const void* p) {
    uint32_t a;
    asm("{ .reg .u64 t; cvta.to.shared.u64 t, %1; cvt.u32.u64 %0, t; }"
        : "=r"(a) : "l"(p));
    return a;
}

__device__ __forceinline__ void mma16816(float* c, const uint32_t* a,
                                         uint32_t b0, uint32_t b1)
{
    asm volatile(
        "mma.sync.aligned.m16n8k16.row.col.f32.bf16.bf16.f32 "
        "{%0,%1,%2,%3}, {%4,%5,%6,%7}, {%8,%9}, {%0,%1,%2,%3};"
        : "+f"(c[0]), "+f"(c[1]), "+f"(c[2]), "+f"(c[3])
        : "r"(a[0]), "r"(a[1]), "r"(a[2]), "r"(a[3]), "r"(b0), "r"(b1));
}

__device__ __forceinline__ void ldsm_x4(uint32_t* r, uint32_t addr) {
    asm volatile("ldmatrix.sync.aligned.m8n8.x4.shared.b16 {%0,%1,%2,%3}, [%4];"
        : "=r"(r[0]), "=r"(r[1]), "=r"(r[2]), "=r"(r[3]) : "r"(addr));
}
__device__ __forceinline__ void ldsm_x4_t(uint32_t* r, uint32_t addr) {
    asm volatile("ldmatrix.sync.aligned.m8n8.x4.trans.shared.b16 {%0,%1,%2,%3}, [%4];"
        : "=r"(r[0]), "=r"(r[1]), "=r"(r[2]), "=r"(r[3]) : "r"(addr));
}

__device__ __forceinline__ uint32_t pack_bf16(float a, float b) {
    __nv_bfloat162 t = __floats2bfloat162_rn(a, b);
    return *(uint32_t*)&t;
}

// ---------------------------------------------------------------------------
// fp32 -> (hi, lo) bf16 split
// ---------------------------------------------------------------------------
__global__ __launch_bounds__(256) void conv_split_kernel(
    const float* __restrict__ src, __nv_bfloat16* __restrict__ hi,
    __nv_bfloat16* __restrict__ lo, int n4)
{
    int i = blockIdx.x * blockDim.x + threadIdx.x;
    if (i >= n4) return;
    float4 v = ((const float4*)src)[i];
    __nv_bfloat16 h0 = __float2bfloat16(v.x);
    __nv_bfloat16 h1 = __float2bfloat16(v.y);
    __nv_bfloat16 h2 = __float2bfloat16(v.z);
    __nv_bfloat16 h3 = __float2bfloat16(v.w);
    __nv_bfloat16 l0 = __float2bfloat16(v.x - __bfloat162float(h0));
    __nv_bfloat16 l1 = __float2bfloat16(v.y - __bfloat162float(h1));
    __nv_bfloat16 l2 = __float2bfloat16(v.z - __bfloat162float(h2));
    __nv_bfloat16 l3 = __float2bfloat16(v.w - __bfloat162float(h3));
    ((__nv_bfloat162*)hi)[2 * i]     = __nv_bfloat162(h0, h1);
    ((__nv_bfloat162*)hi)[2 * i + 1] = __nv_bfloat162(h2, h3);
    ((__nv_bfloat162*)lo)[2 * i]     = __nv_bfloat162(l0, l1);
    ((__nv_bfloat162*)lo)[2 * i + 1] = __nv_bfloat162(l2, l3);
}

// ---------------------------------------------------------------------------
// HMMA GEMM (as R4, but min 2 blocks/SM): C = A*B^T + bias
// ---------------------------------------------------------------------------
#define SSTRIDE 40
__global__ __launch_bounds__(256, 2) void gemm_mma_kernel(
    const __nv_bfloat16* __restrict__ Ahi, const __nv_bfloat16* __restrict__ Alo,
    const __nv_bfloat16* __restrict__ Bhi, const __nv_bfloat16* __restrict__ Blo,
    float* __restrict__ Cm,
    const float* __restrict__ bias_q, const float* __restrict__ bias_v,
    int N, int K, int mode)
{
    extern __shared__ __align__(16) __nv_bfloat16 sm[];
    __nv_bfloat16* sAh = sm;
    __nv_bfloat16* sAl = sAh + 128 * SSTRIDE;
    __nv_bfloat16* sBh = sAl + 128 * SSTRIDE;
    __nv_bfloat16* sBl = sBh + 128 * SSTRIDE;

    int t = threadIdx.x;
    int wid = t >> 5, lane = t & 31;
    int wm = wid & 3, wn = wid >> 2;
    int m0 = blockIdx.y * 128, n0 = blockIdx.x * 128;

    float acc[2][8][4];
    #pragma unroll
    for (int i = 0; i < 2; i++)
        #pragma unroll
        for (int j = 0; j < 8; j++)
            #pragma unroll
            for (int u = 0; u < 4; u++) acc[i][j][u] = 0.f;

    int qrow = lane >> 2;
    int qk   = (lane & 3) * 2;

    for (int k0 = 0; k0 < K; k0 += 32) {
        #pragma unroll
        for (int i = 0; i < 2; i++) {
            int c = t + i * 256;
            int row = c >> 2, seg = c & 3;
            size_t ga = (size_t)(m0 + row) * K + k0 + seg * 8;
            size_t gb = (size_t)(n0 + row) * K + k0 + seg * 8;
            int so = row * SSTRIDE + seg * 8;
            *(uint4*)(sAh + so) = *(const uint4*)(Ahi + ga);
            *(uint4*)(sAl + so) = *(const uint4*)(Alo + ga);
            *(uint4*)(sBh + so) = *(const uint4*)(Bhi + gb);
            *(uint4*)(sBl + so) = *(const uint4*)(Blo + gb);
        }
        __syncthreads();

        #pragma unroll
        for (int ks = 0; ks < 2; ks++) {
            int kk = ks * 16 + qk;
            uint32_t afh[2][4], afl[2][4];
            #pragma unroll
            for (int mf = 0; mf < 2; mf++) {
                int r = wm * 32 + mf * 16 + qrow;
                afh[mf][0] = *(const uint32_t*)(sAh + r * SSTRIDE + kk);
                afh[mf][1] = *(const uint32_t*)(sAh + (r + 8) * SSTRIDE + kk);
                afh[mf][2] = *(const uint32_t*)(sAh + r * SSTRIDE + kk + 8);
                afh[mf][3] = *(const uint32_t*)(sAh + (r + 8) * SSTRIDE + kk + 8);
                afl[mf][0] = *(const uint32_t*)(sAl + r * SSTRIDE + kk);
                afl[mf][1] = *(const uint32_t*)(sAl + (r + 8) * SSTRIDE + kk);
                afl[mf][2] = *(const uint32_t*)(sAl + r * SSTRIDE + kk + 8);
                afl[mf][3] = *(const uint32_t*)(sAl + (r + 8) * SSTRIDE + kk + 8);
            }
            #pragma unroll
            for (int nf = 0; nf < 8; nf++) {
                int nrow = wn * 64 + nf * 8 + qrow;
                uint32_t bh0 = *(const uint32_t*)(sBh + nrow * SSTRIDE + kk);
                uint32_t bh1 = *(const uint32_t*)(sBh + nrow * SSTRIDE + kk + 8);
                uint32_t bl0 = *(const uint32_t*)(sBl + nrow * SSTRIDE + kk);
                uint32_t bl1 = *(const uint32_t*)(sBl + nrow * SSTRIDE + kk + 8);
                #pragma unroll
                for (int mf = 0; mf < 2; mf++) {
                    mma16816(acc[mf][nf], afh[mf], bh0, bh1);
                    mma16816(acc[mf][nf], afh[mf], bl0, bl1);
                    mma16816(acc[mf][nf], afl[mf], bh0, bh1);
                }
            }
        }
        __syncthreads();
    }

    #pragma unroll
    for (int mf = 0; mf < 2; mf++) {
        #pragma unroll
        for (int nf = 0; nf < 8; nf++) {
            int row = m0 + wm * 32 + mf * 16 + qrow;
            int col = n0 + wn * 64 + nf * 8 + qk;
            float bv0, bv1;
            if (mode == 0) {
                bv0 = (col < C_) ? bias_q[col]
                    : ((col < 2 * C_) ? 0.f : bias_v[col - 2 * C_]);
                bv1 = (col + 1 < C_) ? bias_q[col + 1]
                    : ((col + 1 < 2 * C_) ? 0.f : bias_v[col + 1 - 2 * C_]);
            } else {
                bv0 = bias_q[col];
                bv1 = bias_q[col + 1];
            }
            *(float2*)(Cm + (size_t)row * N + col) =
                make_float2(acc[mf][nf][0] + bv0, acc[mf][nf][1] + bv1);
            *(float2*)(Cm + (size_t)(row + 8) * N + col) =
                make_float2(acc[mf][nf][2] + bv0, acc[mf][nf][3] + bv1);
        }
    }
}

// ---------------------------------------------------------------------------
// Transform: l2norm(+scale) + RoPE; writes q/k/v as bf16 hi/lo [b,h,l,d]
// ---------------------------------------------------------------------------
__global__ __launch_bounds__(256) void transform_kernel(
    const float* __restrict__ freqs, const float* __restrict__ sml)
{
    int w    = blockIdx.x * 8 + (threadIdx.x >> 5);
    int lane = threadIdx.x & 31;
    int h = w & 15;
    int l = (w >> 4) & 1023;
    int b = w >> 14;

    const float* base = g_qkv + (size_t)(b * L_ + l) * (3 * C_);
    float2 q2 = ((const float2*)(base + 0 * C_ + h * D_))[lane];
    float2 k2 = ((const float2*)(base + 1 * C_ + h * D_))[lane];
    float2 v2 = ((const float2*)(base + 2 * C_ + h * D_))[lane];

    float qs = q2.x * q2.x + q2.y * q2.y;
    float ks = k2.x * k2.x + k2.y * k2.y;
    #pragma unroll
    for (int o = 16; o > 0; o >>= 1) {
        qs += __shfl_xor_sync(0xffffffffu, qs, o);
        ks += __shfl_xor_sync(0xffffffffu, ks, o);
    }
    float qinv = expf(fminf(sml[h], MAXSC)) / fmaxf(sqrtf(qs), 1e-12f);
    float kinv = 1.f / fmaxf(sqrtf(ks), 1e-12f);

    float2 fc = ((const float2*)(freqs + l * D_))[lane];
    float qx = q2.x * qinv, qy = q2.y * qinv;
    float kx = k2.x * kinv, ky = k2.y * kinv;
    float qox = qx * fc.x - qy * fc.y, qoy = qx * fc.y + qy * fc.x;
    float kox = kx * fc.x - ky * fc.y, koy = kx * fc.y + ky * fc.x;

    size_t oidx = (size_t)((b * H_ + h) * L_ + l) * D_;
    // split hi/lo
    float qhx = __bfloat162float(__float2bfloat16(qox));
    float qhy = __bfloat162float(__float2bfloat16(qoy));
    float khx = __bfloat162float(__float2bfloat16(kox));
    float khy = __bfloat162float(__float2bfloat16(koy));
    float vhx = __bfloat162float(__float2bfloat16(v2.x));
    float vhy = __bfloat162float(__float2bfloat16(v2.y));
    ((uint32_t*)(g_qh + oidx))[lane] = pack_bf16(qox, qoy);
    ((uint32_t*)(g_ql + oidx))[lane] = pack_bf16(qox - qhx, qoy - qhy);
    ((uint32_t*)(g_kh + oidx))[lane] = pack_bf16(kox, koy);
    ((uint32_t*)(g_kl + oidx))[lane] = pack_bf16(kox - khx, koy - khy);
    ((uint32_t*)(g_vh + oidx))[lane] = pack_bf16(v2.x, v2.y);
    ((uint32_t*)(g_vl + oidx))[lane] = pack_bf16(v2.x - vhx, v2.y - vhy);
}

// ---------------------------------------------------------------------------
// Flash attention, bf16 HMMA with 3-term hi/lo splits.
// CTA: 128 threads (4 warps), 64-query tile, 64-key tiles.
// Warp w owns queries [q0 + 16w, q0 + 16w + 16).
// smem: K hi/lo + V hi/lo tiles, [64][72] bf16 each.
// Output written directly as hi/lo bf16 to g_aoh/g_aol [b, l, h*64+d].
// ---------------------------------------------------------------------------
#define AST 72
__global__ __launch_bounds__(128) void attn_mma_kernel(
    const float* __restrict__ bias)
{
    __shared__ __align__(16) __nv_bfloat16 sKh[64 * AST];
    __shared__ __align__(16) __nv_bfloat16 sKl[64 * AST];
    __shared__ __align__(16) __nv_bfloat16 sVh[64 * AST];
    __shared__ __align__(16) __nv_bfloat16 sVl[64 * AST];

    int t = threadIdx.x;
    int wid = t >> 5, lane = t & 31;
    int q0 = blockIdx.x * 64;
    int bh = blockIdx.y;
    int b = bh >> 4, h = bh & 15;

    const __nv_bfloat16* Qh = g_qh + (size_t)bh * L_ * D_;
    const __nv_bfloat16* Ql = g_ql + (size_t)bh * L_ * D_;
    const __nv_bfloat16* Kh = g_kh + (size_t)bh * L_ * D_;
    const __nv_bfloat16* Kl = g_kl + (size_t)bh * L_ * D_;
    const __nv_bfloat16* Vh = g_vh + (size_t)bh * L_ * D_;
    const __nv_bfloat16* Vl = g_vl + (size_t)bh * L_ * D_;

    int rA = q0 + wid * 16 + (lane >> 2);   // global q row for c0/c1
    int c0 = (lane & 3) * 2;

    // Q fragments (persist): 4 k-frags of m16k16
    uint32_t qa_h[4][4], qa_l[4][4];
    #pragma unroll
    for (int kf = 0; kf < 4; kf++) {
        int cb = kf * 16 + c0;
        qa_h[kf][0] = *(const uint32_t*)(Qh + (size_t)rA * D_ + cb);
        qa_h[kf][1] = *(const uint32_t*)(Qh + (size_t)(rA + 8) * D_ + cb);
        qa_h[kf][2] = *(const uint32_t*)(Qh + (size_t)rA * D_ + cb + 8);
        qa_h[kf][3] = *(const uint32_t*)(Qh + (size_t)(rA + 8) * D_ + cb + 8);
        qa_l[kf][0] = *(const uint32_t*)(Ql + (size_t)rA * D_ + cb);
        qa_l[kf][1] = *(const uint32_t*)(Ql + (size_t)(rA + 8) * D_ + cb);
        qa_l[kf][2] = *(const uint32_t*)(Ql + (size_t)rA * D_ + cb + 8);
        qa_l[kf][3] = *(const uint32_t*)(Ql + (size_t)(rA + 8) * D_ + cb + 8);
    }

    float m0 = -CUDART_INF_F, m1 = -CUDART_INF_F;
    float l0 = 0.f, l1 = 0.f;
    float oacc[8][4];
    #pragma unroll
    for (int nf = 0; nf < 8; nf++)
        #pragma unroll
        for (int u = 0; u < 4; u++) oacc[nf][u] = 0.f;

    // ldmatrix lane addressing precompute
    int g = lane >> 3, r8 = lane & 7;
    uint32_t skh = smem_u32(sKh), skl = smem_u32(sKl);
    uint32_t svh = smem_u32(sVh), svl = smem_u32(sVl);
    // K (non-trans): n = 16*nfp + 8*(g>>1) + r8 ; k = 16*kf + 8*(g&1)
    uint32_t koff = 2u * ((uint32_t)((8 * (g >> 1) + r8) * AST + 8 * (g & 1)));
    // V (trans): key = 16*kf + 8*(g&1) + r8 ; d = 16*nfp + 8*(g>>1)
    uint32_t voff = 2u * ((uint32_t)((8 * (g & 1) + r8) * AST + 8 * (g >> 1)));

    const float* brow0 = bias + (size_t)rA * L_;
    const float* brow1 = bias + (size_t)(rA + 8) * L_;

    for (int k0 = 0; k0 < L_; k0 += 64) {
        // Load K/V tiles (hi/lo): 64 rows x 64 bf16 = 512 uint4 chunks each
        #pragma unroll
        for (int i = 0; i < 4; i++) {
            int c = t + i * 128;
            int row = c >> 3, seg = c & 7;
            size_t gsrc = (size_t)(k0 + row) * D_ + seg * 8;
            int so = row * AST + seg * 8;
            *(uint4*)(sKh + so) = *(const uint4*)(Kh + gsrc);
            *(uint4*)(sKl + so) = *(const uint4*)(Kl + gsrc);
            *(uint4*)(sVh + so) = *(const uint4*)(Vh + gsrc);
            *(uint4*)(sVl + so) = *(const uint4*)(Vl + gsrc);
        }
        __syncthreads();

        // S = Q K^T (3 terms)
        float sacc[8][4];
        #pragma unroll
        for (int nf = 0; nf < 8; nf++)
            #pragma unroll
            for (int u = 0; u < 4; u++) sacc[nf][u] = 0.f;

        #pragma unroll
        for (int nfp = 0; nfp < 4; nfp++) {
            #pragma unroll
            for (int kf = 0; kf < 4; kf++) {
                uint32_t stp = 2u * (uint32_t)(16 * nfp * AST + 16 * kf);
                uint32_t bh4[4], bl4[4];
                ldsm_x4(bh4, skh + stp + koff);
                ldsm_x4(bl4, skl + stp + koff);
                mma16816(sacc[2 * nfp],     qa_h[kf], bh4[0], bh4[1]);
                mma16816(sacc[2 * nfp],     qa_h[kf], bl4[0], bl4[1]);
                mma16816(sacc[2 * nfp],     qa_l[kf], bh4[0], bh4[1]);
                mma16816(sacc[2 * nfp + 1], qa_h[kf], bh4[2], bh4[3]);
                mma16816(sacc[2 * nfp + 1], qa_h[kf], bl4[2], bl4[3]);
                mma16816(sacc[2 * nfp + 1], qa_l[kf], bh4[2], bh4[3]);
            }
        }

        // bias add
        #pragma unroll
        for (int nf = 0; nf < 8; nf++) {
            int kc = k0 + nf * 8 + c0;
            float2 b0 = *(const float2*)(brow0 + kc);
            float2 b1 = *(const float2*)(brow1 + kc);
            sacc[nf][0] += b0.x; sacc[nf][1] += b0.y;
            sacc[nf][2] += b1.x; sacc[nf][3] += b1.y;
        }

        // online softmax (rows: c0/c1 -> row A, c2/c3 -> row B)
        float mx0 = -CUDART_INF_F, mx1 = -CUDART_INF_F;
        #pragma unroll
        for (int nf = 0; nf < 8; nf++) {
            mx0 = fmaxf(mx0, fmaxf(sacc[nf][0], sacc[nf][1]));
            mx1 = fmaxf(mx1, fmaxf(sacc[nf][2], sacc[nf][3]));
        }
        mx0 = fmaxf(mx0, __shfl_xor_sync(0xffffffffu, mx0, 1));
        mx0 = fmaxf(mx0, __shfl_xor_sync(0xffffffffu, mx0, 2));
        mx1 = fmaxf(mx1, __shfl_xor_sync(0xffffffffu, mx1, 1));
        mx1 = fmaxf(mx1, __shfl_xor_sync(0xffffffffu, mx1, 2));

        float mn0 = fmaxf(m0, mx0), mn1 = fmaxf(m1, mx1);
        float cr0 = __expf(m0 - mn0), cr1 = __expf(m1 - mn1);
        float rs0 = 0.f, rs1 = 0.f;
        #pragma unroll
        for (int nf = 0; nf < 8; nf++) {
            sacc[nf][0] = __expf(sacc[nf][0] - mn0);
            sacc[nf][1] = __expf(sacc[nf][1] - mn0);
            sacc[nf][2] = __expf(sacc[nf][2] - mn1);
            sacc[nf][3] = __expf(sacc[nf][3] - mn1);
            rs0 += sacc[nf][0] + sacc[nf][1];
            rs1 += sacc[nf][2] + sacc[nf][3];
        }
        rs0 += __shfl_xor_sync(0xffffffffu, rs0, 1);
        rs0 += __shfl_xor_sync(0xffffffffu, rs0, 2);
        rs1 += __shfl_xor_sync(0xffffffffu, rs1, 1);
        rs1 += __shfl_xor_sync(0xffffffffu, rs1, 2);
        l0 = l0 * cr0 + rs0;
        l1 = l1 * cr1 + rs1;
        m0 = mn0; m1 = mn1;

        #pragma unroll
        for (int nf = 0; nf < 8; nf++) {
            oacc[nf][0] *= cr0; oacc[nf][1] *= cr0;
            oacc[nf][2] *= cr1; oacc[nf][3] *= cr1;
        }

        // pack P frags (hi/lo)
        uint32_t pa_h[4][4], pa_l[4][4];
        #pragma unroll
        for (int kf = 0; kf < 4; kf++) {
            #pragma unroll
            for (int half = 0; half < 2; half++) {
                int nf = 2 * kf + half;
                float p0 = sacc[nf][0], p1 = sacc[nf][1];
                float p2 = sacc[nf][2], p3 = sacc[nf][3];
                uint32_t hi01 = pack_bf16(p0, p1);
                uint32_t hi23 = pack_bf16(p2, p3);
                __nv_bfloat162 h01 = *(__nv_bfloat162*)&hi01;
                __nv_bfloat162 h23 = *(__nv_bfloat162*)&hi23;
                uint32_t lo01 = pack_bf16(p0 - __bfloat162float(h01.x),
                                          p1 - __bfloat162float(h01.y));
                uint32_t lo23 = pack_bf16(p2 - __bfloat162float(h23.x),
                                          p3 - __bfloat162float(h23.y));
                pa_h[kf][2 * half]     = hi01;
                pa_h[kf][2 * half + 1] = hi23;
                pa_l[kf][2 * half]     = lo01;
                pa_l[kf][2 * half + 1] = lo23;
            }
        }

        // O += P V (3 terms), V^T frags via ldmatrix.trans
        #pragma unroll
        for (int nfp = 0; nfp < 4; nfp++) {
            #pragma unroll
            for (int kf = 0; kf < 4; kf++) {
                uint32_t stp = 2u * (uint32_t)(16 * kf * AST + 16 * nfp);
                uint32_t vh4[4], vl4[4];
                ldsm_x4_t(vh4, svh + stp + voff);
                ldsm_x4_t(vl4, svl + stp + voff);
                mma16816(oacc[2 * nfp],     pa_h[kf], vh4[0], vh4[1]);
                mma16816(oacc[2 * nfp],     pa_h[kf], vl4[0], vl4[1]);
                mma16816(oacc[2 * nfp],     pa_l[kf], vh4[0], vh4[1]);
                mma16816(oacc[2 * nfp + 1], pa_h[kf], vh4[2], vh4[3]);
                mma16816(oacc[2 * nfp + 1], pa_h[kf], vl4[2], vl4[3]);
                mma16816(oacc[2 * nfp + 1], pa_l[kf], vh4[2], vh4[3]);
            }
        }
        __syncthreads();
    }

    // epilogue: normalize, split hi/lo, write to [b, q, h*64+d]
    float inv0 = 1.f / l0, inv1 = 1.f / l1;
    size_t orow0 = (size_t)(b * L_ + rA) * C_ + h * D_;
    size_t orow1 = (size_t)(b * L_ + rA + 8) * C_ + h * D_;
    #pragma unroll
    for (int nf = 0; nf < 8; nf++) {
        int d = nf * 8 + c0;
        float v0 = oacc[nf][0] * inv0, v1 = oacc[nf][1] * inv0;
        float v2 = oacc[nf][2] * inv1, v3 = oacc[nf][3] * inv1;
        uint32_t h01 = pack_bf16(v0, v1);
        uint32_t h23 = pack_bf16(v2, v3);
        __nv_bfloat162 b01 = *(__nv_bfloat162*)&h01;
        __nv_bfloat162 b23 = *(__nv_bfloat162*)&h23;
        uint32_t l01 = pack_bf16(v0 - __bfloat162float(b01.x),
                                 v1 - __bfloat162float(b01.y));
        uint32_t l23 = pack_bf16(v2 - __bfloat162float(b23.x),
                                 v3 - __bfloat162float(b23.y));
        *(uint32_t*)(g_aoh + orow0 + d) = h01;
        *(uint32_t*)(g_aol + orow0 + d) = l01;
        *(uint32_t*)(g_aoh + orow1 + d) = h23;
        *(uint32_t*)(g_aol + orow1 + d) = l23;
    }
}

// ---------------------------------------------------------------------------
extern "C" void kernel_launch(void* const* d_in, const int* in_sizes, int n_in,
                              void* d_out, int out_size)
{
    const float* x         = (const float*)d_in[0];
    const float* freqs     = (const float*)d_in[1];
    const float* attn_bias = (const float*)d_in[2];
    const float* W_qkv     = (const float*)d_in[3];
    const float* q_bias    = (const float*)d_in[4];
    const float* v_bias    = (const float*)d_in[5];
    const float* sml       = (const float*)d_in[6];
    const float* W_proj    = (const float*)d_in[7];
    const float* b_proj    = (const float*)d_in[8];
    float* out = (float*)d_out;

    void* p;
    cudaGetSymbolAddress(&p, g_qkv); float* qkv = (float*)p;
    cudaGetSymbolAddress(&p, g_xhi); __nv_bfloat16* xhi = (__nv_bfloat16*)p;
    cudaGetSymbolAddress(&p, g_xlo); __nv_bfloat16* xlo = (__nv_bfloat16*)p;
    cudaGetSymbolAddress(&p, g_wqh); __nv_bfloat16* wqh = (__nv_bfloat16*)p;
    cudaGetSymbolAddress(&p, g_wql); __nv_bfloat16* wql = (__nv_bfloat16*)p;
    cudaGetSymbolAddress(&p, g_wph); __nv_bfloat16* wph = (__nv_bfloat16*)p;
    cudaGetSymbolAddress(&p, g_wpl); __nv_bfloat16* wpl = (__nv_bfloat16*)p;
    cudaGetSymbolAddress(&p, g_aoh); __nv_bfloat16* aoh = (__nv_bfloat16*)p;
    cudaGetSymbolAddress(&p, g_aol); __nv_bfloat16* aol = (__nv_bfloat16*)p;

    int gsm = 4 * 128 * SSTRIDE * (int)sizeof(__nv_bfloat16);  // 40960
    static bool attr_set = false;
    if (!attr_set) {
        cudaFuncSetAttribute(gemm_mma_kernel,
                             cudaFuncAttributeMaxDynamicSharedMemorySize, gsm);
        attr_set = true;
    }

    // 0) Split fp32 -> bf16 hi/lo
    conv_split_kernel<<<(B_ * L_ * C_ / 4 + 255) / 256, 256>>>(x, xhi, xlo, B_ * L_ * C_ / 4);
    conv_split_kernel<<<(3 * C_ * C_ / 4 + 255) / 256, 256>>>(W_qkv, wqh, wql, 3 * C_ * C_ / 4);
    conv_split_kernel<<<(C_ * C_ / 4 + 255) / 256, 256>>>(W_proj, wph, wpl, C_ * C_ / 4);

    // 1) QKV GEMM (HMMA)
    gemm_mma_kernel<<<dim3(3 * C_ / 128, B_ * L_ / 128), 256, gsm>>>(
        xhi, xlo, wqh, wql, qkv, q_bias, v_bias, 3 * C_, C_, 0);

    // 2) l2norm + scale + RoPE -> bf16 hi/lo q/k/v
    transform_kernel<<<(B_ * L_ * H_) / 8, 256>>>(freqs, sml);

    // 3) Flash attention (HMMA) -> g_aoh/g_aol
    attn_mma_kernel<<<dim3(L_ / 64, B_ * H_), 128>>>(attn_bias);

    // 4) Proj GEMM (HMMA)
    gemm_mma_kernel<<<dim3(C_ / 128, B_ * L_ / 128), 256, gsm>>>(
        aoh, aol, wph, wpl, out, b_proj, nullptr, C_, C_, 1);
}

// round 6
// speedup vs baseline: 2.7239x; 1.2034x over previous
#include <cuda_runtime.h>
#include <cuda_bf16.h>
#include <math_constants.h>
#include <cstdint>
#include <cstddef>

#define B_ 8
#define L_ 1024
#define C_ 1024
#define H_ 16
#define D_ 64
#define MAXSC 4.6051701859880914f  // log(100)

// ---------------------------------------------------------------------------
// Scratch (bss, no runtime allocation)
// ---------------------------------------------------------------------------
__device__ float g_qkv[B_ * L_ * 3 * C_];

__device__ __nv_bfloat16 g_xhi[B_ * L_ * C_];
__device__ __nv_bfloat16 g_xlo[B_ * L_ * C_];
__device__ __nv_bfloat16 g_wqh[3 * C_ * C_];
__device__ __nv_bfloat16 g_wql[3 * C_ * C_];
__device__ __nv_bfloat16 g_wph[C_ * C_];
__device__ __nv_bfloat16 g_wpl[C_ * C_];

__device__ __nv_bfloat16 g_qh[B_ * H_ * L_ * D_];
__device__ __nv_bfloat16 g_ql[B_ * H_ * L_ * D_];
__device__ __nv_bfloat16 g_kh[B_ * H_ * L_ * D_];
__device__ __nv_bfloat16 g_kl[B_ * H_ * L_ * D_];
__device__ __nv_bfloat16 g_vh[B_ * H_ * L_ * D_];
__device__ __nv_bfloat16 g_vl[B_ * H_ * L_ * D_];

__device__ __nv_bfloat16 g_aoh[B_ * L_ * C_];
__device__ __nv_bfloat16 g_aol[B_ * L_ * C_];

// ---------------------------------------------------------------------------
// Helpers
// ---------------------------------------------------------------------------
__device__ __forceinline__ uint32_t smem_u32(const void* p) {
    uint32_t a;
    asm("{ .reg .u64 t; cvta.to.shared.u64 t, %1; cvt.u32.u64 %0, t; }"
        : "=r"(a) : "l"(p));
    return a;
}

__device__ __forceinline__ void mma16816(float* c, const uint32_t* a,
                                         uint32_t b0, uint32_t b1)
{
    asm volatile(
        "mma.sync.aligned.m16n8k16.row.col.f32.bf16.bf16.f32 "
        "{%0,%1,%2,%3}, {%4,%5,%6,%7}, {%8,%9}, {%0,%1,%2,%3};"
        : "+f"(c[0]), "+f"(c[1]), "+f"(c[2]), "+f"(c[3])
        : "r"(a[0]), "r"(a[1]), "r"(a[2]), "r"(a[3]), "r"(b0), "r"(b1));
}

__device__ __forceinline__ void ldsm_x4(uint32_t* r, uint32_t addr) {
    asm volatile("ldmatrix.sync.aligned.m8n8.x4.shared.b16 {%0,%1,%2,%3}, [%4];"
        : "=r"(r[0]), "=r"(r[1]), "=r"(r[2]), "=r"(r[3]) : "r"(addr));
}
__device__ __forceinline__ void ldsm_x4_t(uint32_t* r, uint32_t addr) {
    asm volatile("ldmatrix.sync.aligned.m8n8.x4.trans.shared.b16 {%0,%1,%2,%3}, [%4];"
        : "=r"(r[0]), "=r"(r[1]), "=r"(r[2]), "=r"(r[3]) : "r"(addr));
}

__device__ __forceinline__ uint32_t pack_bf16(float a, float b) {
    __nv_bfloat162 t = __floats2bfloat162_rn(a, b);
    return *(uint32_t*)&t;
}

__device__ __forceinline__ void cp_async16(uint32_t saddr, const void* gptr) {
    asm volatile("cp.async.cg.shared.global [%0], [%1], 16;"
        :: "r"(saddr), "l"(gptr) : "memory");
}
__device__ __forceinline__ void cp_commit() {
    asm volatile("cp.async.commit_group;" ::: "memory");
}
template <int N>
__device__ __forceinline__ void cp_wait() {
    asm volatile("cp.async.wait_group %0;" :: "n"(N) : "memory");
}

// ---------------------------------------------------------------------------
// fp32 -> (hi, lo) bf16 split
// ---------------------------------------------------------------------------
__global__ __launch_bounds__(256) void conv_split_kernel(
    const float* __restrict__ src, __nv_bfloat16* __restrict__ hi,
    __nv_bfloat16* __restrict__ lo, int n4)
{
    int i = blockIdx.x * blockDim.x + threadIdx.x;
    if (i >= n4) return;
    float4 v = ((const float4*)src)[i];
    __nv_bfloat16 h0 = __float2bfloat16(v.x);
    __nv_bfloat16 h1 = __float2bfloat16(v.y);
    __nv_bfloat16 h2 = __float2bfloat16(v.z);
    __nv_bfloat16 h3 = __float2bfloat16(v.w);
    __nv_bfloat16 l0 = __float2bfloat16(v.x - __bfloat162float(h0));
    __nv_bfloat16 l1 = __float2bfloat16(v.y - __bfloat162float(h1));
    __nv_bfloat16 l2 = __float2bfloat16(v.z - __bfloat162float(h2));
    __nv_bfloat16 l3 = __float2bfloat16(v.w - __bfloat162float(h3));
    ((__nv_bfloat162*)hi)[2 * i]     = __nv_bfloat162(h0, h1);
    ((__nv_bfloat162*)hi)[2 * i + 1] = __nv_bfloat162(h2, h3);
    ((__nv_bfloat162*)lo)[2 * i]     = __nv_bfloat162(l0, l1);
    ((__nv_bfloat162*)lo)[2 * i + 1] = __nv_bfloat162(l2, l3);
}

// ---------------------------------------------------------------------------
// HMMA GEMM, 2-stage cp.async pipeline: C = A*B^T + bias
// ---------------------------------------------------------------------------
#define SSTRIDE 40
#define GMATSZ (128 * SSTRIDE)   // elements per matrix per stage
__global__ __launch_bounds__(256, 2) void gemm_mma_kernel(
    const __nv_bfloat16* __restrict__ Ahi, const __nv_bfloat16* __restrict__ Alo,
    const __nv_bfloat16* __restrict__ Bhi, const __nv_bfloat16* __restrict__ Blo,
    float* __restrict__ Cm,
    const float* __restrict__ bias_q, const float* __restrict__ bias_v,
    int N, int K, int mode)
{
    extern __shared__ __align__(16) __nv_bfloat16 sm[];
    int t = threadIdx.x;
    int wid = t >> 5, lane = t & 31;
    int wm = wid & 3, wn = wid >> 2;
    int m0 = blockIdx.y * 128, n0 = blockIdx.x * 128;
    uint32_t sb = smem_u32(sm);

    float acc[2][8][4];
    #pragma unroll
    for (int i = 0; i < 2; i++)
        #pragma unroll
        for (int j = 0; j < 8; j++)
            #pragma unroll
            for (int u = 0; u < 4; u++) acc[i][j][u] = 0.f;

    int qrow = lane >> 2;
    int qk   = (lane & 3) * 2;
    const int niter = K >> 5;

    auto issue = [&](int it, int s) {
        int k0 = it << 5;
        #pragma unroll
        for (int i = 0; i < 2; i++) {
            int c = t + i * 256;
            int row = c >> 2, seg = c & 3;
            size_t ga = (size_t)(m0 + row) * K + k0 + seg * 8;
            size_t gb = (size_t)(n0 + row) * K + k0 + seg * 8;
            uint32_t so = sb + (uint32_t)(s * 4 * GMATSZ + row * SSTRIDE + seg * 8) * 2;
            cp_async16(so,              Ahi + ga);
            cp_async16(so + GMATSZ * 2, Alo + ga);
            cp_async16(so + GMATSZ * 4, Bhi + gb);
            cp_async16(so + GMATSZ * 6, Blo + gb);
        }
        cp_commit();
    };

    issue(0, 0);
    for (int it = 0; it < niter; it++) {
        int s = it & 1;
        if (it + 1 < niter) { issue(it + 1, s ^ 1); cp_wait<1>(); }
        else                { cp_wait<0>(); }
        __syncthreads();

        const __nv_bfloat16* sAh = sm + s * 4 * GMATSZ;
        const __nv_bfloat16* sAl = sAh + GMATSZ;
        const __nv_bfloat16* sBh = sAl + GMATSZ;
        const __nv_bfloat16* sBl = sBh + GMATSZ;

        #pragma unroll
        for (int ks = 0; ks < 2; ks++) {
            int kk = ks * 16 + qk;
            uint32_t afh[2][4], afl[2][4];
            #pragma unroll
            for (int mf = 0; mf < 2; mf++) {
                int r = wm * 32 + mf * 16 + qrow;
                afh[mf][0] = *(const uint32_t*)(sAh + r * SSTRIDE + kk);
                afh[mf][1] = *(const uint32_t*)(sAh + (r + 8) * SSTRIDE + kk);
                afh[mf][2] = *(const uint32_t*)(sAh + r * SSTRIDE + kk + 8);
                afh[mf][3] = *(const uint32_t*)(sAh + (r + 8) * SSTRIDE + kk + 8);
                afl[mf][0] = *(const uint32_t*)(sAl + r * SSTRIDE + kk);
                afl[mf][1] = *(const uint32_t*)(sAl + (r + 8) * SSTRIDE + kk);
                afl[mf][2] = *(const uint32_t*)(sAl + r * SSTRIDE + kk + 8);
                afl[mf][3] = *(const uint32_t*)(sAl + (r + 8) * SSTRIDE + kk + 8);
            }
            #pragma unroll
            for (int nf = 0; nf < 8; nf++) {
                int nrow = wn * 64 + nf * 8 + qrow;
                uint32_t bh0 = *(const uint32_t*)(sBh + nrow * SSTRIDE + kk);
                uint32_t bh1 = *(const uint32_t*)(sBh + nrow * SSTRIDE + kk + 8);
                uint32_t bl0 = *(const uint32_t*)(sBl + nrow * SSTRIDE + kk);
                uint32_t bl1 = *(const uint32_t*)(sBl + nrow * SSTRIDE + kk + 8);
                #pragma unroll
                for (int mf = 0; mf < 2; mf++) {
                    mma16816(acc[mf][nf], afh[mf], bh0, bh1);
                    mma16816(acc[mf][nf], afh[mf], bl0, bl1);
                    mma16816(acc[mf][nf], afl[mf], bh0, bh1);
                }
            }
        }
        __syncthreads();
    }

    #pragma unroll
    for (int mf = 0; mf < 2; mf++) {
        #pragma unroll
        for (int nf = 0; nf < 8; nf++) {
            int row = m0 + wm * 32 + mf * 16 + qrow;
            int col = n0 + wn * 64 + nf * 8 + qk;
            float bv0, bv1;
            if (mode == 0) {
                bv0 = (col < C_) ? bias_q[col]
                    : ((col < 2 * C_) ? 0.f : bias_v[col - 2 * C_]);
                bv1 = (col + 1 < C_) ? bias_q[col + 1]
                    : ((col + 1 < 2 * C_) ? 0.f : bias_v[col + 1 - 2 * C_]);
            } else {
                bv0 = bias_q[col];
                bv1 = bias_q[col + 1];
            }
            *(float2*)(Cm + (size_t)row * N + col) =
                make_float2(acc[mf][nf][0] + bv0, acc[mf][nf][1] + bv1);
            *(float2*)(Cm + (size_t)(row + 8) * N + col) =
                make_float2(acc[mf][nf][2] + bv0, acc[mf][nf][3] + bv1);
        }
    }
}

// ---------------------------------------------------------------------------
// Transform: l2norm(+scale) + RoPE; writes q/k/v as bf16 hi/lo [b,h,l,d]
// ---------------------------------------------------------------------------
__global__ __launch_bounds__(256) void transform_kernel(
    const float* __restrict__ freqs, const float* __restrict__ sml)
{
    int w    = blockIdx.x * 8 + (threadIdx.x >> 5);
    int lane = threadIdx.x & 31;
    int h = w & 15;
    int l = (w >> 4) & 1023;
    int b = w >> 14;

    const float* base = g_qkv + (size_t)(b * L_ + l) * (3 * C_);
    float2 q2 = ((const float2*)(base + 0 * C_ + h * D_))[lane];
    float2 k2 = ((const float2*)(base + 1 * C_ + h * D_))[lane];
    float2 v2 = ((const float2*)(base + 2 * C_ + h * D_))[lane];

    float qs = q2.x * q2.x + q2.y * q2.y;
    float ks = k2.x * k2.x + k2.y * k2.y;
    #pragma unroll
    for (int o = 16; o > 0; o >>= 1) {
        qs += __shfl_xor_sync(0xffffffffu, qs, o);
        ks += __shfl_xor_sync(0xffffffffu, ks, o);
    }
    float qinv = expf(fminf(sml[h], MAXSC)) / fmaxf(sqrtf(qs), 1e-12f);
    float kinv = 1.f / fmaxf(sqrtf(ks), 1e-12f);

    float2 fc = ((const float2*)(freqs + l * D_))[lane];
    float qx = q2.x * qinv, qy = q2.y * qinv;
    float kx = k2.x * kinv, ky = k2.y * kinv;
    float qox = qx * fc.x - qy * fc.y, qoy = qx * fc.y + qy * fc.x;
    float kox = kx * fc.x - ky * fc.y, koy = kx * fc.y + ky * fc.x;

    size_t oidx = (size_t)((b * H_ + h) * L_ + l) * D_;
    float qhx = __bfloat162float(__float2bfloat16(qox));
    float qhy = __bfloat162float(__float2bfloat16(qoy));
    float khx = __bfloat162float(__float2bfloat16(kox));
    float khy = __bfloat162float(__float2bfloat16(koy));
    float vhx = __bfloat162float(__float2bfloat16(v2.x));
    float vhy = __bfloat162float(__float2bfloat16(v2.y));
    ((uint32_t*)(g_qh + oidx))[lane] = pack_bf16(qox, qoy);
    ((uint32_t*)(g_ql + oidx))[lane] = pack_bf16(qox - qhx, qoy - qhy);
    ((uint32_t*)(g_kh + oidx))[lane] = pack_bf16(kox, koy);
    ((uint32_t*)(g_kl + oidx))[lane] = pack_bf16(kox - khx, koy - khy);
    ((uint32_t*)(g_vh + oidx))[lane] = pack_bf16(v2.x, v2.y);
    ((uint32_t*)(g_vl + oidx))[lane] = pack_bf16(v2.x - vhx, v2.y - vhy);
}

// ---------------------------------------------------------------------------
// Flash attention, bf16 HMMA, 2-stage cp.async pipeline on K/V tiles.
// ---------------------------------------------------------------------------
#define AST 72
#define ATSZ (64 * AST * 2)   // bytes per tile
__global__ __launch_bounds__(128) void attn_mma_kernel(
    const float* __restrict__ bias)
{
    extern __shared__ __align__(16) char asmem[];
    uint32_t sbase = smem_u32(asmem);

    int t = threadIdx.x;
    int wid = t >> 5, lane = t & 31;
    int q0 = blockIdx.x * 64;
    int bh = blockIdx.y;
    int b = bh >> 4, h = bh & 15;

    const __nv_bfloat16* Qh = g_qh + (size_t)bh * L_ * D_;
    const __nv_bfloat16* Ql = g_ql + (size_t)bh * L_ * D_;
    const __nv_bfloat16* Kh = g_kh + (size_t)bh * L_ * D_;
    const __nv_bfloat16* Kl = g_kl + (size_t)bh * L_ * D_;
    const __nv_bfloat16* Vh = g_vh + (size_t)bh * L_ * D_;
    const __nv_bfloat16* Vl = g_vl + (size_t)bh * L_ * D_;

    int rA = q0 + wid * 16 + (lane >> 2);
    int c0 = (lane & 3) * 2;

    uint32_t qa_h[4][4], qa_l[4][4];
    #pragma unroll
    for (int kf = 0; kf < 4; kf++) {
        int cb = kf * 16 + c0;
        qa_h[kf][0] = *(const uint32_t*)(Qh + (size_t)rA * D_ + cb);
        qa_h[kf][1] = *(const uint32_t*)(Qh + (size_t)(rA + 8) * D_ + cb);
        qa_h[kf][2] = *(const uint32_t*)(Qh + (size_t)rA * D_ + cb + 8);
        qa_h[kf][3] = *(const uint32_t*)(Qh + (size_t)(rA + 8) * D_ + cb + 8);
        qa_l[kf][0] = *(const uint32_t*)(Ql + (size_t)rA * D_ + cb);
        qa_l[kf][1] = *(const uint32_t*)(Ql + (size_t)(rA + 8) * D_ + cb);
        qa_l[kf][2] = *(const uint32_t*)(Ql + (size_t)rA * D_ + cb + 8);
        qa_l[kf][3] = *(const uint32_t*)(Ql + (size_t)(rA + 8) * D_ + cb + 8);
    }

    float m0 = -CUDART_INF_F, m1 = -CUDART_INF_F;
    float l0 = 0.f, l1 = 0.f;
    float oacc[8][4];
    #pragma unroll
    for (int nf = 0; nf < 8; nf++)
        #pragma unroll
        for (int u = 0; u < 4; u++) oacc[nf][u] = 0.f;

    int g = lane >> 3, r8 = lane & 7;
    uint32_t koff = 2u * ((uint32_t)((8 * (g >> 1) + r8) * AST + 8 * (g & 1)));
    uint32_t voff = 2u * ((uint32_t)((8 * (g & 1) + r8) * AST + 8 * (g >> 1)));

    const float* brow0 = bias + (size_t)rA * L_;
    const float* brow1 = bias + (size_t)(rA + 8) * L_;

    auto issue_kv = [&](int k0, int s) {
        #pragma unroll
        for (int i = 0; i < 4; i++) {
            int c = t + i * 128;
            int row = c >> 3, seg = c & 7;
            size_t gsrc = (size_t)(k0 + row) * D_ + seg * 8;
            uint32_t so = sbase + (uint32_t)(s * 4) * ATSZ
                        + (uint32_t)(row * AST + seg * 8) * 2;
            cp_async16(so,            Kh + gsrc);
            cp_async16(so + ATSZ,     Kl + gsrc);
            cp_async16(so + 2 * ATSZ, Vh + gsrc);
            cp_async16(so + 3 * ATSZ, Vl + gsrc);
        }
        cp_commit();
    };

    issue_kv(0, 0);
    const int NIT = L_ / 64;
    for (int ki = 0; ki < NIT; ki++) {
        int s = ki & 1;
        if (ki + 1 < NIT) { issue_kv((ki + 1) * 64, s ^ 1); cp_wait<1>(); }
        else              { cp_wait<0>(); }
        __syncthreads();

        uint32_t skh = sbase + (uint32_t)(s * 4) * ATSZ;
        uint32_t skl = skh + ATSZ;
        uint32_t svh = skl + ATSZ;
        uint32_t svl = svh + ATSZ;
        int k0 = ki * 64;

        float sacc[8][4];
        #pragma unroll
        for (int nf = 0; nf < 8; nf++)
            #pragma unroll
            for (int u = 0; u < 4; u++) sacc[nf][u] = 0.f;

        #pragma unroll
        for (int nfp = 0; nfp < 4; nfp++) {
            #pragma unroll
            for (int kf = 0; kf < 4; kf++) {
                uint32_t stp = 2u * (uint32_t)(16 * nfp * AST + 16 * kf);
                uint32_t bh4[4], bl4[4];
                ldsm_x4(bh4, skh + stp + koff);
                ldsm_x4(bl4, skl + stp + koff);
                mma16816(sacc[2 * nfp],     qa_h[kf], bh4[0], bh4[1]);
                mma16816(sacc[2 * nfp],     qa_h[kf], bl4[0], bl4[1]);
                mma16816(sacc[2 * nfp],     qa_l[kf], bh4[0], bh4[1]);
                mma16816(sacc[2 * nfp + 1], qa_h[kf], bh4[2], bh4[3]);
                mma16816(sacc[2 * nfp + 1], qa_h[kf], bl4[2], bl4[3]);
                mma16816(sacc[2 * nfp + 1], qa_l[kf], bh4[2], bh4[3]);
            }
        }

        #pragma unroll
        for (int nf = 0; nf < 8; nf++) {
            int kc = k0 + nf * 8 + c0;
            float2 b0 = *(const float2*)(brow0 + kc);
            float2 b1 = *(const float2*)(brow1 + kc);
            sacc[nf][0] += b0.x; sacc[nf][1] += b0.y;
            sacc[nf][2] += b1.x; sacc[nf][3] += b1.y;
        }

        float mx0 = -CUDART_INF_F, mx1 = -CUDART_INF_F;
        #pragma unroll
        for (int nf = 0; nf < 8; nf++) {
            mx0 = fmaxf(mx0, fmaxf(sacc[nf][0], sacc[nf][1]));
            mx1 = fmaxf(mx1, fmaxf(sacc[nf][2], sacc[nf][3]));
        }
        mx0 = fmaxf(mx0, __shfl_xor_sync(0xffffffffu, mx0, 1));
        mx0 = fmaxf(mx0, __shfl_xor_sync(0xffffffffu, mx0, 2));
        mx1 = fmaxf(mx1, __shfl_xor_sync(0xffffffffu, mx1, 1));
        mx1 = fmaxf(mx1, __shfl_xor_sync(0xffffffffu, mx1, 2));

        float mn0 = fmaxf(m0, mx0), mn1 = fmaxf(m1, mx1);
        float cr0 = __expf(m0 - mn0), cr1 = __expf(m1 - mn1);
        float rs0 = 0.f, rs1 = 0.f;
        #pragma unroll
        for (int nf = 0; nf < 8; nf++) {
            sacc[nf][0] = __expf(sacc[nf][0] - mn0);
            sacc[nf][1] = __expf(sacc[nf][1] - mn0);
            sacc[nf][2] = __expf(sacc[nf][2] - mn1);
            sacc[nf][3] = __expf(sacc[nf][3] - mn1);
            rs0 += sacc[nf][0] + sacc[nf][1];
            rs1 += sacc[nf][2] + sacc[nf][3];
        }
        rs0 += __shfl_xor_sync(0xffffffffu, rs0, 1);
        rs0 += __shfl_xor_sync(0xffffffffu, rs0, 2);
        rs1 += __shfl_xor_sync(0xffffffffu, rs1, 1);
        rs1 += __shfl_xor_sync(0xffffffffu, rs1, 2);
        l0 = l0 * cr0 + rs0;
        l1 = l1 * cr1 + rs1;
        m0 = mn0; m1 = mn1;

        #pragma unroll
        for (int nf = 0; nf < 8; nf++) {
            oacc[nf][0] *= cr0; oacc[nf][1] *= cr0;
            oacc[nf][2] *= cr1; oacc[nf][3] *= cr1;
        }

        uint32_t pa_h[4][4], pa_l[4][4];
        #pragma unroll
        for (int kf = 0; kf < 4; kf++) {
            #pragma unroll
            for (int half = 0; half < 2; half++) {
                int nf = 2 * kf + half;
                float p0 = sacc[nf][0], p1 = sacc[nf][1];
                float p2 = sacc[nf][2], p3 = sacc[nf][3];
                uint32_t hi01 = pack_bf16(p0, p1);
                uint32_t hi23 = pack_bf16(p2, p3);
                __nv_bfloat162 h01 = *(__nv_bfloat162*)&hi01;
                __nv_bfloat162 h23 = *(__nv_bfloat162*)&hi23;
                uint32_t lo01 = pack_bf16(p0 - __bfloat162float(h01.x),
                                          p1 - __bfloat162float(h01.y));
                uint32_t lo23 = pack_bf16(p2 - __bfloat162float(h23.x),
                                          p3 - __bfloat162float(h23.y));
                pa_h[kf][2 * half]     = hi01;
                pa_h[kf][2 * half + 1] = hi23;
                pa_l[kf][2 * half]     = lo01;
                pa_l[kf][2 * half + 1] = lo23;
            }
        }

        #pragma unroll
        for (int nfp = 0; nfp < 4; nfp++) {
            #pragma unroll
            for (int kf = 0; kf < 4; kf++) {
                uint32_t stp = 2u * (uint32_t)(16 * kf * AST + 16 * nfp);
                uint32_t vh4[4], vl4[4];
                ldsm_x4_t(vh4, svh + stp + voff);
                ldsm_x4_t(vl4, svl + stp + voff);
                mma16816(oacc[2 * nfp],     pa_h[kf], vh4[0], vh4[1]);
                mma16816(oacc[2 * nfp],     pa_h[kf], vl4[0], vl4[1]);
                mma16816(oacc[2 * nfp],     pa_l[kf], vh4[0], vh4[1]);
                mma16816(oacc[2 * nfp + 1], pa_h[kf], vh4[2], vh4[3]);
                mma16816(oacc[2 * nfp + 1], pa_h[kf], vl4[2], vl4[3]);
                mma16816(oacc[2 * nfp + 1], pa_l[kf], vh4[2], vh4[3]);
            }
        }
        __syncthreads();
    }

    float inv0 = 1.f / l0, inv1 = 1.f / l1;
    size_t orow0 = (size_t)(b * L_ + rA) * C_ + h * D_;
    size_t orow1 = (size_t)(b * L_ + rA + 8) * C_ + h * D_;
    #pragma unroll
    for (int nf = 0; nf < 8; nf++) {
        int d = nf * 8 + c0;
        float v0 = oacc[nf][0] * inv0, v1 = oacc[nf][1] * inv0;
        float v2 = oacc[nf][2] * inv1, v3 = oacc[nf][3] * inv1;
        uint32_t h01 = pack_bf16(v0, v1);
        uint32_t h23 = pack_bf16(v2, v3);
        __nv_bfloat162 b01 = *(__nv_bfloat162*)&h01;
        __nv_bfloat162 b23 = *(__nv_bfloat162*)&h23;
        uint32_t l01 = pack_bf16(v0 - __bfloat162float(b01.x),
                                 v1 - __bfloat162float(b01.y));
        uint32_t l23 = pack_bf16(v2 - __bfloat162float(b23.x),
                                 v3 - __bfloat162float(b23.y));
        *(uint32_t*)(g_aoh + orow0 + d) = h01;
        *(uint32_t*)(g_aol + orow0 + d) = l01;
        *(uint32_t*)(g_aoh + orow1 + d) = h23;
        *(uint32_t*)(g_aol + orow1 + d) = l23;
    }
}

// ---------------------------------------------------------------------------
extern "C" void kernel_launch(void* const* d_in, const int* in_sizes, int n_in,
                              void* d_out, int out_size)
{
    const float* x         = (const float*)d_in[0];
    const float* freqs     = (const float*)d_in[1];
    const float* attn_bias = (const float*)d_in[2];
    const float* W_qkv     = (const float*)d_in[3];
    const float* q_bias    = (const float*)d_in[4];
    const float* v_bias    = (const float*)d_in[5];
    const float* sml       = (const float*)d_in[6];
    const float* W_proj    = (const float*)d_in[7];
    const float* b_proj    = (const float*)d_in[8];
    float* out = (float*)d_out;

    void* p;
    cudaGetSymbolAddress(&p, g_qkv); float* qkv = (float*)p;
    cudaGetSymbolAddress(&p, g_xhi); __nv_bfloat16* xhi = (__nv_bfloat16*)p;
    cudaGetSymbolAddress(&p, g_xlo); __nv_bfloat16* xlo = (__nv_bfloat16*)p;
    cudaGetSymbolAddress(&p, g_wqh); __nv_bfloat16* wqh = (__nv_bfloat16*)p;
    cudaGetSymbolAddress(&p, g_wql); __nv_bfloat16* wql = (__nv_bfloat16*)p;
    cudaGetSymbolAddress(&p, g_wph); __nv_bfloat16* wph = (__nv_bfloat16*)p;
    cudaGetSymbolAddress(&p, g_wpl); __nv_bfloat16* wpl = (__nv_bfloat16*)p;
    cudaGetSymbolAddress(&p, g_aoh); __nv_bfloat16* aoh = (__nv_bfloat16*)p;
    cudaGetSymbolAddress(&p, g_aol); __nv_bfloat16* aol = (__nv_bfloat16*)p;

    int gsm = 2 * 4 * GMATSZ * (int)sizeof(__nv_bfloat16);  // 81920
    int asm_ = 2 * 4 * ATSZ;                                 // 73728
    static bool attr_set = false;
    if (!attr_set) {
        cudaFuncSetAttribute(gemm_mma_kernel,
                             cudaFuncAttributeMaxDynamicSharedMemorySize, gsm);
        cudaFuncSetAttribute(attn_mma_kernel,
                             cudaFuncAttributeMaxDynamicSharedMemorySize, asm_);
        attr_set = true;
    }

    conv_split_kernel<<<(B_ * L_ * C_ / 4 + 255) / 256, 256>>>(x, xhi, xlo, B_ * L_ * C_ / 4);
    conv_split_kernel<<<(3 * C_ * C_ / 4 + 255) / 256, 256>>>(W_qkv, wqh, wql, 3 * C_ * C_ / 4);
    conv_split_kernel<<<(C_ * C_ / 4 + 255) / 256, 256>>>(W_proj, wph, wpl, C_ * C_ / 4);

    gemm_mma_kernel<<<dim3(3 * C_ / 128, B_ * L_ / 128), 256, gsm>>>(
        xhi, xlo, wqh, wql, qkv, q_bias, v_bias, 3 * C_, C_, 0);

    transform_kernel<<<(B_ * L_ * H_) / 8, 256>>>(freqs, sml);

    attn_mma_kernel<<<dim3(L_ / 64, B_ * H_), 128, asm_>>>(attn_bias);

    gemm_mma_kernel<<<dim3(C_ / 128, B_ * L_ / 128), 256, gsm>>>(
        aoh, aol, wph, wpl, out, b_proj, nullptr, C_, C_, 1);
}